// round 11
// baseline (speedup 1.0000x reference)
#include <cuda_runtime.h>
#include <cuda_bf16.h>

#define CDIM   256
#define CDIM4  64          // CDIM/4
#define NV_MAX 20000
#define ME_MAX 4000
#define NNZ_MAX 160000
#define CAP_E  192         // padded CSR capacity per edge   (mean 40)
#define CAP_V  64          // padded CSR capacity per vertex (mean 8)
#define WN_MAX ((NV_MAX + 31) / 32)   // 625 words for the per-edge vertex bitmap
#define EG_SPLIT 2048      // row split point for the eg->GEMM pipeline (multiple of BM)

// -------------------- static device scratch --------------------
__device__ float4 d_Y4[ME_MAX * CDIM4];    // edge-aggregated RAW X (unscaled)   [4 MB]
__device__ float4 d_XeP4[ME_MAX * CDIM4];  // projected+scaled edge features     [4 MB]
__device__ int   d_curE[ME_MAX];           // atomic cursors == raw counts
__device__ int   d_curV[NV_MAX];
__device__ int   d_csrEp[ME_MAX * CAP_E];  // padded: vertices of edge e
__device__ int   d_csrVp[NV_MAX * CAP_V];  // padded: edges of vertex v
__device__ float d_degV[NV_MAX];           // rsqrt(distinct-edge count) or 1
__device__ float d_sE[ME_MAX];             // rsqrt(distinct-vertex cnt) / (rawcnt + 1e-8)

// -------------------- padded CSR fill, x8 ILP (no count/scan) --------------------
__global__ void fillE_kernel(const int4* __restrict__ vertex4, const int4* __restrict__ edges4,
                             int nnz4)
{
    int k = blockIdx.x * blockDim.x + threadIdx.x;   // pair index
    int k0 = k * 2;
    if (k0 >= nnz4) return;
    int4 v = vertex4[k0];
    int4 e = edges4[k0];
    int p;
    p = atomicAdd(&d_curE[e.x], 1); if (p < CAP_E) d_csrEp[e.x * CAP_E + p] = v.x;
    p = atomicAdd(&d_curE[e.y], 1); if (p < CAP_E) d_csrEp[e.y * CAP_E + p] = v.y;
    p = atomicAdd(&d_curE[e.z], 1); if (p < CAP_E) d_csrEp[e.z * CAP_E + p] = v.z;
    p = atomicAdd(&d_curE[e.w], 1); if (p < CAP_E) d_csrEp[e.w * CAP_E + p] = v.w;
    int k1 = k0 + 1;
    if (k1 >= nnz4) return;
    int4 v1 = vertex4[k1];
    int4 e1 = edges4[k1];
    p = atomicAdd(&d_curE[e1.x], 1); if (p < CAP_E) d_csrEp[e1.x * CAP_E + p] = v1.x;
    p = atomicAdd(&d_curE[e1.y], 1); if (p < CAP_E) d_csrEp[e1.y * CAP_E + p] = v1.y;
    p = atomicAdd(&d_curE[e1.z], 1); if (p < CAP_E) d_csrEp[e1.z * CAP_E + p] = v1.z;
    p = atomicAdd(&d_curE[e1.w], 1); if (p < CAP_E) d_csrEp[e1.w * CAP_E + p] = v1.w;
}
__global__ void fillV_kernel(const int4* __restrict__ vertex4, const int4* __restrict__ edges4,
                             int nnz4)
{
    int k = blockIdx.x * blockDim.x + threadIdx.x;   // pair index
    int k0 = k * 2;
    if (k0 >= nnz4) return;
    int4 v = vertex4[k0];
    int4 e = edges4[k0];
    int q;
    q = atomicAdd(&d_curV[v.x], 1); if (q < CAP_V) d_csrVp[v.x * CAP_V + q] = e.x;
    q = atomicAdd(&d_curV[v.y], 1); if (q < CAP_V) d_csrVp[v.y * CAP_V + q] = e.y;
    q = atomicAdd(&d_curV[v.z], 1); if (q < CAP_V) d_csrVp[v.z * CAP_V + q] = e.z;
    q = atomicAdd(&d_curV[v.w], 1); if (q < CAP_V) d_csrVp[v.w * CAP_V + q] = e.w;
    int k1 = k0 + 1;
    if (k1 >= nnz4) return;
    int4 v1 = vertex4[k1];
    int4 e1 = edges4[k1];
    q = atomicAdd(&d_curV[v1.x], 1); if (q < CAP_V) d_csrVp[v1.x * CAP_V + q] = e1.x;
    q = atomicAdd(&d_curV[v1.y], 1); if (q < CAP_V) d_csrVp[v1.y * CAP_V + q] = e1.y;
    q = atomicAdd(&d_curV[v1.z], 1); if (q < CAP_V) d_csrVp[v1.z * CAP_V + q] = e1.z;
    q = atomicAdd(&d_curV[v1.w], 1); if (q < CAP_V) d_csrVp[v1.w * CAP_V + q] = e1.w;
}

// -------------------- dedupE: shared-memory bitmap, block per edge, O(n) ----------------
__global__ __launch_bounds__(128)
void dedupE_kernel(int wn)     // wn = (Nv+31)/32
{
    __shared__ unsigned bm[WN_MAX];
    __shared__ int wsum[4];
    int e = blockIdx.x;
    int tid = threadIdx.x;
    for (int i = tid; i < wn; i += 128) bm[i] = 0u;
    __syncthreads();
    int cnt = d_curE[e];
    int n = min(cnt, CAP_E);
    int base = e * CAP_E;
    int mine = 0;
    for (int i = tid; i < n; i += 128) {
        int v = d_csrEp[base + i];
        unsigned bit = 1u << (v & 31);
        unsigned old = atomicOr(&bm[v >> 5], bit);
        if (!(old & bit)) mine++;
    }
    mine = __reduce_add_sync(0xffffffffu, mine);
    if ((tid & 31) == 0) wsum[tid >> 5] = mine;
    __syncthreads();
    if (tid == 0) {
        int distinct = wsum[0] + wsum[1] + wsum[2] + wsum[3];
        d_sE[e] = rsqrtf((float)distinct) / ((float)cnt + 1e-8f);
    }
}

// -------------------- dedupV: O(n^2) warp per vertex (rows ~8, fully overlapped) --------
__global__ void dedupV_kernel(int Nv)
{
    int v = (blockIdx.x * blockDim.x + threadIdx.x) >> 5;
    int lane = threadIdx.x & 31;
    if (v >= Nv) return;
    int cnt = d_curV[v];
    int n = min(cnt, CAP_V);
    int base = v * CAP_V;
    int distinct = 0;
    for (int i = lane; i < n; i += 32) {
        int val = d_csrVp[base + i];
        bool dup = false;
        for (int j = 0; j < i; j++)
            if (d_csrVp[base + j] == val) { dup = true; break; }
        if (!dup) distinct++;
    }
    distinct = __reduce_add_sync(0xffffffffu, distinct);
    if (lane == 0)
        d_degV[v] = (distinct == 0) ? 1.0f : rsqrtf((float)distinct);
}

// -------------------- vertex -> edge on RAW X: plain sum (scale folded into GEMM) --------
__global__ __launch_bounds__(CDIM4)
void edge_gather_kernel(const float4* __restrict__ X4, int eBase)
{
    int e = eBase + blockIdx.x;
    int c = threadIdx.x;                 // 0..63
    int n = min(d_curE[e], CAP_E);
    int base = e * CAP_E;
    float4 acc = make_float4(0.f,0.f,0.f,0.f);
    int i = 0;
    for (; i + 4 <= n; i += 4) {
        float4 p0 = X4[(long)d_csrEp[base + i + 0] * CDIM4 + c];
        float4 p1 = X4[(long)d_csrEp[base + i + 1] * CDIM4 + c];
        float4 p2 = X4[(long)d_csrEp[base + i + 2] * CDIM4 + c];
        float4 p3 = X4[(long)d_csrEp[base + i + 3] * CDIM4 + c];
        acc.x += (p0.x + p1.x) + (p2.x + p3.x);
        acc.y += (p0.y + p1.y) + (p2.y + p3.y);
        acc.z += (p0.z + p1.z) + (p2.z + p3.z);
        acc.w += (p0.w + p1.w) + (p2.w + p3.w);
    }
    for (; i < n; i++) {
        float4 p = X4[(long)d_csrEp[base + i] * CDIM4 + c];
        acc.x += p.x; acc.y += p.y; acc.z += p.z; acc.w += p.w;
    }
    d_Y4[(long)e * CDIM4 + c] = acc;
}

// -------------------- SGEMM: XeP = (Y @ W^T) * sE[row], row-chunked ---------------------
#define BM 128
#define BN 64
#define BK 16

__global__ __launch_bounds__(256)
void sgemm_kernel(const float* __restrict__ A, const float* __restrict__ B,
                  float* __restrict__ Cmat, int Nrows, int rowBase)
{
    __shared__ float As[2][BK][BM];
    __shared__ float Bs[2][BK][BN];

    const int tid = threadIdx.x;
    const int brow0 = rowBase + blockIdx.x * BM;
    const int bcol0 = blockIdx.y * BN;
    const int tx = tid & 15;
    const int ty = tid >> 4;

    float4 c0 = make_float4(0.f,0.f,0.f,0.f);
    float4 c1 = c0, c2 = c0, c3 = c0, c4 = c0, c5 = c0, c6 = c0, c7 = c0;

    const int a0row = tid >> 2;
    const int a1row = a0row + 64;
    const int lk4   = (tid & 3) * 4;
    const int ga0 = brow0 + a0row;
    const int ga1 = brow0 + a1row;
    const bool av0 = (ga0 < Nrows);
    const bool av1 = (ga1 < Nrows);
    const int gb  = bcol0 + a0row;
    const float4 z4 = make_float4(0.f,0.f,0.f,0.f);

    {
        float4 va0 = av0 ? *(const float4*)&A[(long)ga0 * CDIM + lk4] : z4;
        float4 va1 = av1 ? *(const float4*)&A[(long)ga1 * CDIM + lk4] : z4;
        float4 vb  = *(const float4*)&B[(long)gb * CDIM + lk4];
        As[0][lk4 + 0][a0row] = va0.x;  As[0][lk4 + 1][a0row] = va0.y;
        As[0][lk4 + 2][a0row] = va0.z;  As[0][lk4 + 3][a0row] = va0.w;
        As[0][lk4 + 0][a1row] = va1.x;  As[0][lk4 + 1][a1row] = va1.y;
        As[0][lk4 + 2][a1row] = va1.z;  As[0][lk4 + 3][a1row] = va1.w;
        Bs[0][lk4 + 0][a0row] = vb.x;   Bs[0][lk4 + 1][a0row] = vb.y;
        Bs[0][lk4 + 2][a0row] = vb.z;   Bs[0][lk4 + 3][a0row] = vb.w;
    }
    __syncthreads();

    int buf = 0;
#pragma unroll 1
    for (int t = 0; t < CDIM / BK; t++) {
        float4 na0, na1, nb;
        const bool more = (t < CDIM / BK - 1);
        if (more) {
            int kt = (t + 1) * BK;
            na0 = av0 ? *(const float4*)&A[(long)ga0 * CDIM + kt + lk4] : z4;
            na1 = av1 ? *(const float4*)&A[(long)ga1 * CDIM + kt + lk4] : z4;
            nb  = *(const float4*)&B[(long)gb * CDIM + kt + lk4];
        }
#pragma unroll
        for (int k = 0; k < BK; k++) {
            float4 af0 = *(const float4*)&As[buf][k][ty * 8];
            float4 af1 = *(const float4*)&As[buf][k][ty * 8 + 4];
            float4 bf  = *(const float4*)&Bs[buf][k][tx * 4];
            c0.x += af0.x * bf.x; c0.y += af0.x * bf.y; c0.z += af0.x * bf.z; c0.w += af0.x * bf.w;
            c1.x += af0.y * bf.x; c1.y += af0.y * bf.y; c1.z += af0.y * bf.z; c1.w += af0.y * bf.w;
            c2.x += af0.z * bf.x; c2.y += af0.z * bf.y; c2.z += af0.z * bf.z; c2.w += af0.z * bf.w;
            c3.x += af0.w * bf.x; c3.y += af0.w * bf.y; c3.z += af0.w * bf.z; c3.w += af0.w * bf.w;
            c4.x += af1.x * bf.x; c4.y += af1.x * bf.y; c4.z += af1.x * bf.z; c4.w += af1.x * bf.w;
            c5.x += af1.y * bf.x; c5.y += af1.y * bf.y; c5.z += af1.y * bf.z; c5.w += af1.y * bf.w;
            c6.x += af1.z * bf.x; c6.y += af1.z * bf.y; c6.z += af1.z * bf.z; c6.w += af1.z * bf.w;
            c7.x += af1.w * bf.x; c7.y += af1.w * bf.y; c7.z += af1.w * bf.z; c7.w += af1.w * bf.w;
        }
        if (more) {
            int nbuf = buf ^ 1;
            As[nbuf][lk4 + 0][a0row] = na0.x;  As[nbuf][lk4 + 1][a0row] = na0.y;
            As[nbuf][lk4 + 2][a0row] = na0.z;  As[nbuf][lk4 + 3][a0row] = na0.w;
            As[nbuf][lk4 + 0][a1row] = na1.x;  As[nbuf][lk4 + 1][a1row] = na1.y;
            As[nbuf][lk4 + 2][a1row] = na1.z;  As[nbuf][lk4 + 3][a1row] = na1.w;
            Bs[nbuf][lk4 + 0][a0row] = nb.x;   Bs[nbuf][lk4 + 1][a0row] = nb.y;
            Bs[nbuf][lk4 + 2][a0row] = nb.z;   Bs[nbuf][lk4 + 3][a0row] = nb.w;
        }
        __syncthreads();
        buf ^= 1;
    }

    const int orow = brow0 + ty * 8;
    const int ocol = bcol0 + tx * 4;
    if (orow + 0 < Nrows) { float s = d_sE[orow + 0];
        *(float4*)&Cmat[(long)(orow + 0) * CDIM + ocol] = make_float4(c0.x*s, c0.y*s, c0.z*s, c0.w*s); }
    if (orow + 1 < Nrows) { float s = d_sE[orow + 1];
        *(float4*)&Cmat[(long)(orow + 1) * CDIM + ocol] = make_float4(c1.x*s, c1.y*s, c1.z*s, c1.w*s); }
    if (orow + 2 < Nrows) { float s = d_sE[orow + 2];
        *(float4*)&Cmat[(long)(orow + 2) * CDIM + ocol] = make_float4(c2.x*s, c2.y*s, c2.z*s, c2.w*s); }
    if (orow + 3 < Nrows) { float s = d_sE[orow + 3];
        *(float4*)&Cmat[(long)(orow + 3) * CDIM + ocol] = make_float4(c3.x*s, c3.y*s, c3.z*s, c3.w*s); }
    if (orow + 4 < Nrows) { float s = d_sE[orow + 4];
        *(float4*)&Cmat[(long)(orow + 4) * CDIM + ocol] = make_float4(c4.x*s, c4.y*s, c4.z*s, c4.w*s); }
    if (orow + 5 < Nrows) { float s = d_sE[orow + 5];
        *(float4*)&Cmat[(long)(orow + 5) * CDIM + ocol] = make_float4(c5.x*s, c5.y*s, c5.z*s, c5.w*s); }
    if (orow + 6 < Nrows) { float s = d_sE[orow + 6];
        *(float4*)&Cmat[(long)(orow + 6) * CDIM + ocol] = make_float4(c6.x*s, c6.y*s, c6.z*s, c6.w*s); }
    if (orow + 7 < Nrows) { float s = d_sE[orow + 7];
        *(float4*)&Cmat[(long)(orow + 7) * CDIM + ocol] = make_float4(c7.x*s, c7.y*s, c7.z*s, c7.w*s); }
}

// -------------------- edge -> vertex: sum of projected edge rows + vertex norm ----------
__global__ __launch_bounds__(CDIM4)
void vertex_gather_kernel(float4* __restrict__ out4)
{
    int v = blockIdx.x;
    int c = threadIdx.x;                 // 0..63
    int n = min(d_curV[v], CAP_V);
    int base = v * CAP_V;
    float dv = d_degV[v];
    float4 acc = make_float4(0.f,0.f,0.f,0.f);
    int i = 0;
    for (; i + 4 <= n; i += 4) {
        float4 p0 = d_XeP4[(long)d_csrVp[base + i + 0] * CDIM4 + c];
        float4 p1 = d_XeP4[(long)d_csrVp[base + i + 1] * CDIM4 + c];
        float4 p2 = d_XeP4[(long)d_csrVp[base + i + 2] * CDIM4 + c];
        float4 p3 = d_XeP4[(long)d_csrVp[base + i + 3] * CDIM4 + c];
        acc.x += (p0.x + p1.x) + (p2.x + p3.x);
        acc.y += (p0.y + p1.y) + (p2.y + p3.y);
        acc.z += (p0.z + p1.z) + (p2.z + p3.z);
        acc.w += (p0.w + p1.w) + (p2.w + p3.w);
    }
    for (; i < n; i++) {
        float4 p = d_XeP4[(long)d_csrVp[base + i] * CDIM4 + c];
        acc.x += p.x; acc.y += p.y; acc.z += p.z; acc.w += p.w;
    }
    out4[(long)v * CDIM4 + c] = make_float4(acc.x * dv, acc.y * dv, acc.z * dv, acc.w * dv);
}

__global__ void noop_kernel() {}

// -------------------- launch --------------------
extern "C" void kernel_launch(void* const* d_in, const int* in_sizes, int n_in,
                              void* d_out, int out_size)
{
    const float* X      = (const float*)d_in[0];
    const float* W      = (const float*)d_in[1];
    const int*   vertex = (const int*)d_in[2];
    const int*   edges  = (const int*)d_in[3];
    float* out = (float*)d_out;

    int Nv  = in_sizes[0] / CDIM;             // 20000
    int NNZ = in_sizes[2];                    // 160000
    int Me  = (int)((long)in_sizes[4] / Nv);  // 4000
    int nnz4 = NNZ / 4;
    int nnz8 = (nnz4 + 1) / 2;                // thread count for x8 fill
    int wn = (Nv + 31) / 32;

    int split = (Me > EG_SPLIT) ? EG_SPLIT : (Me / BM / 2) * BM;  // BM-aligned row split
    if (split <= 0) split = Me;

    // one-time host-side resources (no device allocations)
    static cudaStream_t s2 = nullptr, s3 = nullptr, s4 = nullptr;
    static cudaEvent_t evFork = nullptr, evFillE = nullptr, evSE = nullptr,
                       evJoinV = nullptr, evEG0 = nullptr, evG0 = nullptr;
    static float *pY = nullptr, *pXeP = nullptr;
    static int *pCurE = nullptr, *pCurV = nullptr;
    if (s2 == nullptr) {
        cudaStreamCreateWithFlags(&s2, cudaStreamNonBlocking);
        cudaStreamCreateWithFlags(&s3, cudaStreamNonBlocking);
        cudaStreamCreateWithFlags(&s4, cudaStreamNonBlocking);
        cudaEventCreateWithFlags(&evFork,  cudaEventDisableTiming);
        cudaEventCreateWithFlags(&evFillE, cudaEventDisableTiming);
        cudaEventCreateWithFlags(&evSE,    cudaEventDisableTiming);
        cudaEventCreateWithFlags(&evJoinV, cudaEventDisableTiming);
        cudaEventCreateWithFlags(&evEG0,   cudaEventDisableTiming);
        cudaEventCreateWithFlags(&evG0,    cudaEventDisableTiming);
        cudaGetSymbolAddress((void**)&pY,    d_Y4);
        cudaGetSymbolAddress((void**)&pXeP,  d_XeP4);
        cudaGetSymbolAddress((void**)&pCurE, d_curE);
        cudaGetSymbolAddress((void**)&pCurV, d_curV);
    }

    // fork for the V-chain
    cudaEventRecord(evFork, 0);
    cudaStreamWaitEvent(s2, evFork, 0);

    // V-chain (only needed by final vertex_gather): zero cursors -> fill -> dedup
    cudaMemsetAsync(pCurV, 0, (size_t)Nv * sizeof(int), s2);
    fillV_kernel<<<(nnz8 + 255) / 256, 256, 0, s2>>>((const int4*)vertex, (const int4*)edges, nnz4);
    dedupV_kernel<<<(Nv * 32 + 255) / 256, 256, 0, s2>>>(Nv);
    cudaEventRecord(evJoinV, s2);

    // main: E-chain
    cudaMemsetAsync(pCurE, 0, (size_t)Me * sizeof(int), 0);
    fillE_kernel<<<(nnz8 + 255) / 256, 256>>>((const int4*)vertex, (const int4*)edges, nnz4);
    cudaEventRecord(evFillE, 0);

    // dedupE (O(n) bitmap) concurrent with edge_gather on s3
    cudaStreamWaitEvent(s3, evFillE, 0);
    dedupE_kernel<<<Me, 128, 0, s3>>>(wn);
    cudaEventRecord(evSE, s3);

    // edge_gather half 0 (edges [0, split)), then half 1 -- pipelined with GEMM half 0
    edge_gather_kernel<<<split, CDIM4>>>((const float4*)X, 0);
    cudaEventRecord(evEG0, 0);
    edge_gather_kernel<<<Me - split, CDIM4>>>((const float4*)X, split);

    // GEMM half 0 on s4: rows [0, split); needs eg half 0 + sE
    cudaStreamWaitEvent(s4, evEG0, 0);
    cudaStreamWaitEvent(s4, evSE, 0);
    {
        dim3 g0(split / BM, CDIM / BN);
        sgemm_kernel<<<g0, 256, 0, s4>>>(pY, W, pXeP, Me, 0);
    }
    cudaEventRecord(evG0, s4);

    // GEMM half 1 on main: rows [split, Me); needs eg half 1 (program order) + sE
    cudaStreamWaitEvent(0, evSE, 0);
    {
        dim3 g1((Me - split + BM - 1) / BM, CDIM / BN);
        sgemm_kernel<<<g1, 256>>>(pY, W, pXeP, Me, split);
    }

    // vertex_gather needs both GEMM halves + V-side CSR/degrees
    cudaStreamWaitEvent(0, evG0, 0);
    cudaStreamWaitEvent(0, evJoinV, 0);
    vertex_gather_kernel<<<Nv, CDIM4>>>((float4*)out);
}

// round 13
// speedup vs baseline: 1.4120x; 1.4120x over previous
#include <cuda_runtime.h>
#include <cuda_fp16.h>

#define CDIM   256
#define CDIM4  64          // CDIM/4
#define CDIMH2 128         // CDIM/2 (half2 count per row)
#define NV_MAX 20000
#define ME_MAX 4000
#define NNZ_MAX 160000
#define CAP_E  192         // padded CSR capacity per edge   (mean 40)
#define CAP_V  64          // padded CSR capacity per vertex (mean 8)

// -------------------- static device scratch --------------------
__device__ float4 d_Y4[ME_MAX * CDIM4];     // edge-aggregated RAW X (unscaled)    [4 MB]
__device__ __half2 d_XeH[ME_MAX * CDIMH2];  // projected+scaled edge feats (fp16)  [2 MB]
__device__ int   d_curE[ME_MAX];            // atomic cursors == raw counts
__device__ int   d_curV[NV_MAX];
__device__ int   d_csrEp[ME_MAX * CAP_E];   // padded: vertices of edge e
__device__ int   d_csrVp[NV_MAX * CAP_V];   // padded: edges of vertex v
__device__ float d_degV[NV_MAX];            // rsqrt(distinct-edge count) or 1
__device__ float d_sE[ME_MAX];              // rsqrt(distinct-vertex cnt) / (rawcnt + 1e-8)

// -------------------- padded CSR fill, x4 ILP (no count/scan) --------------------
__global__ void fillE_kernel(const int4* __restrict__ vertex4, const int4* __restrict__ edges4,
                             int nnz4)
{
    int k = blockIdx.x * blockDim.x + threadIdx.x;
    if (k >= nnz4) return;
    int4 v = vertex4[k];
    int4 e = edges4[k];
    int p;
    p = atomicAdd(&d_curE[e.x], 1); if (p < CAP_E) d_csrEp[e.x * CAP_E + p] = v.x;
    p = atomicAdd(&d_curE[e.y], 1); if (p < CAP_E) d_csrEp[e.y * CAP_E + p] = v.y;
    p = atomicAdd(&d_curE[e.z], 1); if (p < CAP_E) d_csrEp[e.z * CAP_E + p] = v.z;
    p = atomicAdd(&d_curE[e.w], 1); if (p < CAP_E) d_csrEp[e.w * CAP_E + p] = v.w;
}
__global__ void fillV_kernel(const int4* __restrict__ vertex4, const int4* __restrict__ edges4,
                             int nnz4)
{
    int k = blockIdx.x * blockDim.x + threadIdx.x;
    if (k >= nnz4) return;
    int4 v = vertex4[k];
    int4 e = edges4[k];
    int q;
    q = atomicAdd(&d_curV[v.x], 1); if (q < CAP_V) d_csrVp[v.x * CAP_V + q] = e.x;
    q = atomicAdd(&d_curV[v.y], 1); if (q < CAP_V) d_csrVp[v.y * CAP_V + q] = e.y;
    q = atomicAdd(&d_curV[v.z], 1); if (q < CAP_V) d_csrVp[v.z * CAP_V + q] = e.z;
    q = atomicAdd(&d_curV[v.w], 1); if (q < CAP_V) d_csrVp[v.w * CAP_V + q] = e.w;
}

// -------------------- dedupE: O(n^2) warp per edge (overlapped with edge_gather) --------
__global__ void dedupE_kernel(int Me)
{
    int e = (blockIdx.x * blockDim.x + threadIdx.x) >> 5;
    int lane = threadIdx.x & 31;
    if (e >= Me) return;
    int cnt = d_curE[e];
    int n = min(cnt, CAP_E);
    int base = e * CAP_E;
    int distinct = 0;
    for (int i = lane; i < n; i += 32) {
        int val = d_csrEp[base + i];
        bool dup = false;
        for (int j = 0; j < i; j++)
            if (d_csrEp[base + j] == val) { dup = true; break; }
        if (!dup) distinct++;
    }
    distinct = __reduce_add_sync(0xffffffffu, distinct);
    if (lane == 0)
        d_sE[e] = rsqrtf((float)distinct) / ((float)cnt + 1e-8f);
}

// -------------------- dedupV: O(n^2) warp per vertex (rows ~8, fully overlapped) --------
__global__ void dedupV_kernel(int Nv)
{
    int v = (blockIdx.x * blockDim.x + threadIdx.x) >> 5;
    int lane = threadIdx.x & 31;
    if (v >= Nv) return;
    int cnt = d_curV[v];
    int n = min(cnt, CAP_V);
    int base = v * CAP_V;
    int distinct = 0;
    for (int i = lane; i < n; i += 32) {
        int val = d_csrVp[base + i];
        bool dup = false;
        for (int j = 0; j < i; j++)
            if (d_csrVp[base + j] == val) { dup = true; break; }
        if (!dup) distinct++;
    }
    distinct = __reduce_add_sync(0xffffffffu, distinct);
    if (lane == 0)
        d_degV[v] = (distinct == 0) ? 1.0f : rsqrtf((float)distinct);
}

// -------------------- vertex -> edge on RAW X: plain sum (scale folded into GEMM) --------
__global__ __launch_bounds__(CDIM4)
void edge_gather_kernel(const float4* __restrict__ X4)
{
    int e = blockIdx.x;
    int c = threadIdx.x;                 // 0..63
    int n = min(d_curE[e], CAP_E);
    int base = e * CAP_E;
    float4 acc = make_float4(0.f,0.f,0.f,0.f);
    int i = 0;
    for (; i + 4 <= n; i += 4) {
        float4 p0 = X4[(long)d_csrEp[base + i + 0] * CDIM4 + c];
        float4 p1 = X4[(long)d_csrEp[base + i + 1] * CDIM4 + c];
        float4 p2 = X4[(long)d_csrEp[base + i + 2] * CDIM4 + c];
        float4 p3 = X4[(long)d_csrEp[base + i + 3] * CDIM4 + c];
        acc.x += (p0.x + p1.x) + (p2.x + p3.x);
        acc.y += (p0.y + p1.y) + (p2.y + p3.y);
        acc.z += (p0.z + p1.z) + (p2.z + p3.z);
        acc.w += (p0.w + p1.w) + (p2.w + p3.w);
    }
    for (; i < n; i++) {
        float4 p = X4[(long)d_csrEp[base + i] * CDIM4 + c];
        acc.x += p.x; acc.y += p.y; acc.z += p.z; acc.w += p.w;
    }
    d_Y4[(long)e * CDIM4 + c] = acc;
}

// -------------------- SGEMM: XeH = fp16((Y @ W^T) * sE[row])  (M=4000, K=256) -----------
#define BM 128
#define BN 64
#define BK 16

__global__ __launch_bounds__(256)
void sgemm_kernel(const float* __restrict__ A, const float* __restrict__ B, int Nrows)
{
    __shared__ float As[2][BK][BM];
    __shared__ float Bs[2][BK][BN];

    const int tid = threadIdx.x;
    const int brow0 = blockIdx.x * BM;
    const int bcol0 = blockIdx.y * BN;
    const int tx = tid & 15;
    const int ty = tid >> 4;

    float4 c0 = make_float4(0.f,0.f,0.f,0.f);
    float4 c1 = c0, c2 = c0, c3 = c0, c4 = c0, c5 = c0, c6 = c0, c7 = c0;

    const int a0row = tid >> 2;
    const int a1row = a0row + 64;
    const int lk4   = (tid & 3) * 4;
    const int ga0 = brow0 + a0row;
    const int ga1 = brow0 + a1row;
    const bool av0 = (ga0 < Nrows);
    const bool av1 = (ga1 < Nrows);
    const int gb  = bcol0 + a0row;
    const float4 z4 = make_float4(0.f,0.f,0.f,0.f);

    {
        float4 va0 = av0 ? *(const float4*)&A[(long)ga0 * CDIM + lk4] : z4;
        float4 va1 = av1 ? *(const float4*)&A[(long)ga1 * CDIM + lk4] : z4;
        float4 vb  = *(const float4*)&B[(long)gb * CDIM + lk4];
        As[0][lk4 + 0][a0row] = va0.x;  As[0][lk4 + 1][a0row] = va0.y;
        As[0][lk4 + 2][a0row] = va0.z;  As[0][lk4 + 3][a0row] = va0.w;
        As[0][lk4 + 0][a1row] = va1.x;  As[0][lk4 + 1][a1row] = va1.y;
        As[0][lk4 + 2][a1row] = va1.z;  As[0][lk4 + 3][a1row] = va1.w;
        Bs[0][lk4 + 0][a0row] = vb.x;   Bs[0][lk4 + 1][a0row] = vb.y;
        Bs[0][lk4 + 2][a0row] = vb.z;   Bs[0][lk4 + 3][a0row] = vb.w;
    }
    __syncthreads();

    int buf = 0;
#pragma unroll 1
    for (int t = 0; t < CDIM / BK; t++) {
        float4 na0, na1, nb;
        const bool more = (t < CDIM / BK - 1);
        if (more) {
            int kt = (t + 1) * BK;
            na0 = av0 ? *(const float4*)&A[(long)ga0 * CDIM + kt + lk4] : z4;
            na1 = av1 ? *(const float4*)&A[(long)ga1 * CDIM + kt + lk4] : z4;
            nb  = *(const float4*)&B[(long)gb * CDIM + kt + lk4];
        }
#pragma unroll
        for (int k = 0; k < BK; k++) {
            float4 af0 = *(const float4*)&As[buf][k][ty * 8];
            float4 af1 = *(const float4*)&As[buf][k][ty * 8 + 4];
            float4 bf  = *(const float4*)&Bs[buf][k][tx * 4];
            c0.x += af0.x * bf.x; c0.y += af0.x * bf.y; c0.z += af0.x * bf.z; c0.w += af0.x * bf.w;
            c1.x += af0.y * bf.x; c1.y += af0.y * bf.y; c1.z += af0.y * bf.z; c1.w += af0.y * bf.w;
            c2.x += af0.z * bf.x; c2.y += af0.z * bf.y; c2.z += af0.z * bf.z; c2.w += af0.z * bf.w;
            c3.x += af0.w * bf.x; c3.y += af0.w * bf.y; c3.z += af0.w * bf.z; c3.w += af0.w * bf.w;
            c4.x += af1.x * bf.x; c4.y += af1.x * bf.y; c4.z += af1.x * bf.z; c4.w += af1.x * bf.w;
            c5.x += af1.y * bf.x; c5.y += af1.y * bf.y; c5.z += af1.y * bf.z; c5.w += af1.y * bf.w;
            c6.x += af1.z * bf.x; c6.y += af1.z * bf.y; c6.z += af1.z * bf.z; c6.w += af1.z * bf.w;
            c7.x += af1.w * bf.x; c7.y += af1.w * bf.y; c7.z += af1.w * bf.z; c7.w += af1.w * bf.w;
        }
        if (more) {
            int nbuf = buf ^ 1;
            As[nbuf][lk4 + 0][a0row] = na0.x;  As[nbuf][lk4 + 1][a0row] = na0.y;
            As[nbuf][lk4 + 2][a0row] = na0.z;  As[nbuf][lk4 + 3][a0row] = na0.w;
            As[nbuf][lk4 + 0][a1row] = na1.x;  As[nbuf][lk4 + 1][a1row] = na1.y;
            As[nbuf][lk4 + 2][a1row] = na1.z;  As[nbuf][lk4 + 3][a1row] = na1.w;
            Bs[nbuf][lk4 + 0][a0row] = nb.x;   Bs[nbuf][lk4 + 1][a0row] = nb.y;
            Bs[nbuf][lk4 + 2][a0row] = nb.z;   Bs[nbuf][lk4 + 3][a0row] = nb.w;
        }
        __syncthreads();
        buf ^= 1;
    }

    const int orow = brow0 + ty * 8;
    const int oc2  = (bcol0 + tx * 4) >> 1;   // half2 column index (even)
    // epilogue: scale by sE[row], convert fp32->fp16, store 4 halves as one uint2
#define STORE_ROW(CR, RIDX)                                                  \
    if (orow + RIDX < Nrows) {                                               \
        float s = d_sE[orow + RIDX];                                         \
        __half2 h0 = __floats2half2_rn(CR.x * s, CR.y * s);                  \
        __half2 h1 = __floats2half2_rn(CR.z * s, CR.w * s);                  \
        unsigned u0 = *reinterpret_cast<unsigned*>(&h0);                     \
        unsigned u1 = *reinterpret_cast<unsigned*>(&h1);                     \
        *reinterpret_cast<uint2*>(&d_XeH[(long)(orow + RIDX) * CDIMH2 + oc2])\
            = make_uint2(u0, u1);                                            \
    }
    STORE_ROW(c0, 0) STORE_ROW(c1, 1) STORE_ROW(c2, 2) STORE_ROW(c3, 3)
    STORE_ROW(c4, 4) STORE_ROW(c5, 5) STORE_ROW(c6, 6) STORE_ROW(c7, 7)
#undef STORE_ROW
}

// -------------------- edge -> vertex: fp16 rows summed in fp32 + vertex norm ------------
__global__ __launch_bounds__(CDIM4)
void vertex_gather_kernel(float4* __restrict__ out4)
{
    int v = blockIdx.x;
    int c = threadIdx.x;                 // 0..63  -> uint2 (4 halves) per row
    int n = min(d_curV[v], CAP_V);
    int base = v * CAP_V;
    float dv = d_degV[v];
    float2 accLo = make_float2(0.f, 0.f);
    float2 accHi = make_float2(0.f, 0.f);
    int i = 0;
    for (; i + 4 <= n; i += 4) {
        uint2 r0 = *reinterpret_cast<const uint2*>(&d_XeH[(long)d_csrVp[base + i + 0] * CDIMH2 + c * 2]);
        uint2 r1 = *reinterpret_cast<const uint2*>(&d_XeH[(long)d_csrVp[base + i + 1] * CDIMH2 + c * 2]);
        uint2 r2 = *reinterpret_cast<const uint2*>(&d_XeH[(long)d_csrVp[base + i + 2] * CDIMH2 + c * 2]);
        uint2 r3 = *reinterpret_cast<const uint2*>(&d_XeH[(long)d_csrVp[base + i + 3] * CDIMH2 + c * 2]);
        float2 a0 = __half22float2(*reinterpret_cast<__half2*>(&r0.x));
        float2 b0 = __half22float2(*reinterpret_cast<__half2*>(&r0.y));
        float2 a1 = __half22float2(*reinterpret_cast<__half2*>(&r1.x));
        float2 b1 = __half22float2(*reinterpret_cast<__half2*>(&r1.y));
        float2 a2 = __half22float2(*reinterpret_cast<__half2*>(&r2.x));
        float2 b2 = __half22float2(*reinterpret_cast<__half2*>(&r2.y));
        float2 a3 = __half22float2(*reinterpret_cast<__half2*>(&r3.x));
        float2 b3 = __half22float2(*reinterpret_cast<__half2*>(&r3.y));
        accLo.x += (a0.x + a1.x) + (a2.x + a3.x);
        accLo.y += (a0.y + a1.y) + (a2.y + a3.y);
        accHi.x += (b0.x + b1.x) + (b2.x + b3.x);
        accHi.y += (b0.y + b1.y) + (b2.y + b3.y);
    }
    for (; i < n; i++) {
        uint2 r = *reinterpret_cast<const uint2*>(&d_XeH[(long)d_csrVp[base + i] * CDIMH2 + c * 2]);
        float2 a = __half22float2(*reinterpret_cast<__half2*>(&r.x));
        float2 b = __half22float2(*reinterpret_cast<__half2*>(&r.y));
        accLo.x += a.x; accLo.y += a.y;
        accHi.x += b.x; accHi.y += b.y;
    }
    out4[(long)v * CDIM4 + c] =
        make_float4(accLo.x * dv, accLo.y * dv, accHi.x * dv, accHi.y * dv);
}

// -------------------- launch (Round-8 schedule, verbatim) --------------------
extern "C" void kernel_launch(void* const* d_in, const int* in_sizes, int n_in,
                              void* d_out, int out_size)
{
    const float* X      = (const float*)d_in[0];
    const float* W      = (const float*)d_in[1];
    const int*   vertex = (const int*)d_in[2];
    const int*   edges  = (const int*)d_in[3];
    float* out = (float*)d_out;

    int Nv  = in_sizes[0] / CDIM;             // 20000
    int NNZ = in_sizes[2];                    // 160000
    int Me  = (int)((long)in_sizes[4] / Nv);  // 4000
    int nnz4 = NNZ / 4;

    // one-time host-side resources (no device allocations)
    static cudaStream_t s2 = nullptr, s3 = nullptr;
    static cudaEvent_t evFork = nullptr, evFillE = nullptr, evSE = nullptr, evJoinV = nullptr;
    static float *pY = nullptr;
    static int *pCurE = nullptr, *pCurV = nullptr;
    if (s2 == nullptr) {
        cudaStreamCreateWithFlags(&s2, cudaStreamNonBlocking);
        cudaStreamCreateWithFlags(&s3, cudaStreamNonBlocking);
        cudaEventCreateWithFlags(&evFork,  cudaEventDisableTiming);
        cudaEventCreateWithFlags(&evFillE, cudaEventDisableTiming);
        cudaEventCreateWithFlags(&evSE,    cudaEventDisableTiming);
        cudaEventCreateWithFlags(&evJoinV, cudaEventDisableTiming);
        cudaGetSymbolAddress((void**)&pY,    d_Y4);
        cudaGetSymbolAddress((void**)&pCurE, d_curE);
        cudaGetSymbolAddress((void**)&pCurV, d_curV);
    }

    // fork for the V-chain
    cudaEventRecord(evFork, 0);
    cudaStreamWaitEvent(s2, evFork, 0);

    // V-chain (only needed by final vertex_gather): zero cursors -> fill -> dedup
    cudaMemsetAsync(pCurV, 0, (size_t)Nv * sizeof(int), s2);
    fillV_kernel<<<(nnz4 + 255) / 256, 256, 0, s2>>>((const int4*)vertex, (const int4*)edges, nnz4);
    dedupV_kernel<<<(Nv * 32 + 255) / 256, 256, 0, s2>>>(Nv);
    cudaEventRecord(evJoinV, s2);

    // main: E-chain -> edge_gather -> GEMM
    cudaMemsetAsync(pCurE, 0, (size_t)Me * sizeof(int), 0);
    fillE_kernel<<<(nnz4 + 255) / 256, 256>>>((const int4*)vertex, (const int4*)edges, nnz4);
    cudaEventRecord(evFillE, 0);

    // dedupE runs concurrently with edge_gather on s3 (GEMM consumes sE in its epilogue)
    cudaStreamWaitEvent(s3, evFillE, 0);
    dedupE_kernel<<<(Me * 32 + 255) / 256, 256, 0, s3>>>(Me);
    cudaEventRecord(evSE, s3);

    edge_gather_kernel<<<Me, CDIM4>>>((const float4*)X);

    cudaStreamWaitEvent(0, evSE, 0);
    dim3 ggrid((Me + BM - 1) / BM, CDIM / BN);
    sgemm_kernel<<<ggrid, 256>>>(pY, W, Me);

    cudaStreamWaitEvent(0, evJoinV, 0);
    vertex_gather_kernel<<<Nv, CDIM4>>>((float4*)out);
}

// round 14
// speedup vs baseline: 1.4548x; 1.0303x over previous
#include <cuda_runtime.h>

#define CDIM   256
#define CDIM4  64          // CDIM/4
#define NV_MAX 20000
#define ME_MAX 4000
#define NNZ_MAX 160000
#define CAP_E  192         // padded CSR capacity per edge   (mean 40)
#define CAP_V  64          // padded CSR capacity per vertex (mean 8)
#define WN_MAX ((NV_MAX + 31) / 32)   // 625 words for the per-edge vertex bitmap

// -------------------- static device scratch --------------------
__device__ float4 d_Y4[ME_MAX * CDIM4];    // edge-aggregated X, pre-scaled by sE  [4 MB]
__device__ float4 d_XeP4[ME_MAX * CDIM4];  // projected edge features              [4 MB]
__device__ int   d_cur[ME_MAX + NV_MAX];   // atomic cursors: [0,Me) = E, [Me,Me+Nv) = V
__device__ int   d_csrEp[ME_MAX * CAP_E];  // padded: vertices of edge e
__device__ int   d_csrVp[NV_MAX * CAP_V];  // padded: edges of vertex v

// -------------------- fused padded CSR fill (E and V in one pass) --------------------
__global__ void fill_kernel(const int4* __restrict__ vertex4, const int4* __restrict__ edges4,
                            int nnz4, int Me)
{
    int k = blockIdx.x * blockDim.x + threadIdx.x;
    if (k >= nnz4) return;
    int4 v = vertex4[k];
    int4 e = edges4[k];
    int p;
    p = atomicAdd(&d_cur[e.x], 1); if (p < CAP_E) d_csrEp[e.x * CAP_E + p] = v.x;
    p = atomicAdd(&d_cur[e.y], 1); if (p < CAP_E) d_csrEp[e.y * CAP_E + p] = v.y;
    p = atomicAdd(&d_cur[e.z], 1); if (p < CAP_E) d_csrEp[e.z * CAP_E + p] = v.z;
    p = atomicAdd(&d_cur[e.w], 1); if (p < CAP_E) d_csrEp[e.w * CAP_E + p] = v.w;
    p = atomicAdd(&d_cur[Me + v.x], 1); if (p < CAP_V) d_csrVp[v.x * CAP_V + p] = e.x;
    p = atomicAdd(&d_cur[Me + v.y], 1); if (p < CAP_V) d_csrVp[v.y * CAP_V + p] = e.y;
    p = atomicAdd(&d_cur[Me + v.z], 1); if (p < CAP_V) d_csrVp[v.z * CAP_V + p] = e.z;
    p = atomicAdd(&d_cur[Me + v.w], 1); if (p < CAP_V) d_csrVp[v.w * CAP_V + p] = e.w;
}

// -------- vertex -> edge gather + fused dedupE (bitmap) + sE scale, block per edge ------
__global__ __launch_bounds__(CDIM4)
void edge_gather_kernel(const float4* __restrict__ X4, int wn)
{
    __shared__ unsigned bm[WN_MAX];
    __shared__ int s_idx[CAP_E];
    __shared__ int wsum[2];
    __shared__ float s_scale;

    int e = blockIdx.x;
    int tid = threadIdx.x;               // 0..63
    int cnt = d_cur[e];
    int n = min(cnt, CAP_E);
    int base = e * CAP_E;

    for (int i = tid; i < wn; i += CDIM4) bm[i] = 0u;
    __syncthreads();

    // pass 1: cache indices in smem + count distinct via bitmap
    int mine = 0;
    for (int i = tid; i < n; i += CDIM4) {
        int v = d_csrEp[base + i];
        s_idx[i] = v;
        unsigned bit = 1u << (v & 31);
        unsigned old = atomicOr(&bm[v >> 5], bit);
        if (!(old & bit)) mine++;
    }
    mine = __reduce_add_sync(0xffffffffu, mine);
    if ((tid & 31) == 0) wsum[tid >> 5] = mine;
    __syncthreads();
    if (tid == 0) {
        int distinct = wsum[0] + wsum[1];
        s_scale = rsqrtf((float)distinct) / ((float)cnt + 1e-8f);
    }
    __syncthreads();

    // pass 2: gather-sum the X rows (indices from smem), scale, store
    float s = s_scale;
    float4 acc = make_float4(0.f, 0.f, 0.f, 0.f);
    int i = 0;
    for (; i + 4 <= n; i += 4) {
        float4 p0 = X4[(long)s_idx[i + 0] * CDIM4 + tid];
        float4 p1 = X4[(long)s_idx[i + 1] * CDIM4 + tid];
        float4 p2 = X4[(long)s_idx[i + 2] * CDIM4 + tid];
        float4 p3 = X4[(long)s_idx[i + 3] * CDIM4 + tid];
        acc.x += (p0.x + p1.x) + (p2.x + p3.x);
        acc.y += (p0.y + p1.y) + (p2.y + p3.y);
        acc.z += (p0.z + p1.z) + (p2.z + p3.z);
        acc.w += (p0.w + p1.w) + (p2.w + p3.w);
    }
    for (; i < n; i++) {
        float4 p = X4[(long)s_idx[i] * CDIM4 + tid];
        acc.x += p.x; acc.y += p.y; acc.z += p.z; acc.w += p.w;
    }
    d_Y4[(long)e * CDIM4 + tid] = make_float4(acc.x * s, acc.y * s, acc.z * s, acc.w * s);
}

// -------------------- SGEMM: XeP = Y @ W^T  (M=4000, K=256), double-buffered ------------
#define BM 128
#define BN 64
#define BK 16

__global__ __launch_bounds__(256)
void sgemm_kernel(const float* __restrict__ A, const float* __restrict__ B,
                  float* __restrict__ Cmat, int Nrows)
{
    __shared__ float As[2][BK][BM];
    __shared__ float Bs[2][BK][BN];

    const int tid = threadIdx.x;
    const int brow0 = blockIdx.x * BM;
    const int bcol0 = blockIdx.y * BN;
    const int tx = tid & 15;
    const int ty = tid >> 4;

    float4 c0 = make_float4(0.f,0.f,0.f,0.f);
    float4 c1 = c0, c2 = c0, c3 = c0, c4 = c0, c5 = c0, c6 = c0, c7 = c0;

    const int a0row = tid >> 2;
    const int a1row = a0row + 64;
    const int lk4   = (tid & 3) * 4;
    const int ga0 = brow0 + a0row;
    const int ga1 = brow0 + a1row;
    const bool av0 = (ga0 < Nrows);
    const bool av1 = (ga1 < Nrows);
    const int gb  = bcol0 + a0row;
    const float4 z4 = make_float4(0.f,0.f,0.f,0.f);

    {
        float4 va0 = av0 ? *(const float4*)&A[(long)ga0 * CDIM + lk4] : z4;
        float4 va1 = av1 ? *(const float4*)&A[(long)ga1 * CDIM + lk4] : z4;
        float4 vb  = *(const float4*)&B[(long)gb * CDIM + lk4];
        As[0][lk4 + 0][a0row] = va0.x;  As[0][lk4 + 1][a0row] = va0.y;
        As[0][lk4 + 2][a0row] = va0.z;  As[0][lk4 + 3][a0row] = va0.w;
        As[0][lk4 + 0][a1row] = va1.x;  As[0][lk4 + 1][a1row] = va1.y;
        As[0][lk4 + 2][a1row] = va1.z;  As[0][lk4 + 3][a1row] = va1.w;
        Bs[0][lk4 + 0][a0row] = vb.x;   Bs[0][lk4 + 1][a0row] = vb.y;
        Bs[0][lk4 + 2][a0row] = vb.z;   Bs[0][lk4 + 3][a0row] = vb.w;
    }
    __syncthreads();

    int buf = 0;
#pragma unroll 1
    for (int t = 0; t < CDIM / BK; t++) {
        float4 na0, na1, nb;
        const bool more = (t < CDIM / BK - 1);
        if (more) {
            int kt = (t + 1) * BK;
            na0 = av0 ? *(const float4*)&A[(long)ga0 * CDIM + kt + lk4] : z4;
            na1 = av1 ? *(const float4*)&A[(long)ga1 * CDIM + kt + lk4] : z4;
            nb  = *(const float4*)&B[(long)gb * CDIM + kt + lk4];
        }
#pragma unroll
        for (int k = 0; k < BK; k++) {
            float4 af0 = *(const float4*)&As[buf][k][ty * 8];
            float4 af1 = *(const float4*)&As[buf][k][ty * 8 + 4];
            float4 bf  = *(const float4*)&Bs[buf][k][tx * 4];
            c0.x += af0.x * bf.x; c0.y += af0.x * bf.y; c0.z += af0.x * bf.z; c0.w += af0.x * bf.w;
            c1.x += af0.y * bf.x; c1.y += af0.y * bf.y; c1.z += af0.y * bf.z; c1.w += af0.y * bf.w;
            c2.x += af0.z * bf.x; c2.y += af0.z * bf.y; c2.z += af0.z * bf.z; c2.w += af0.z * bf.w;
            c3.x += af0.w * bf.x; c3.y += af0.w * bf.y; c3.z += af0.w * bf.z; c3.w += af0.w * bf.w;
            c4.x += af1.x * bf.x; c4.y += af1.x * bf.y; c4.z += af1.x * bf.z; c4.w += af1.x * bf.w;
            c5.x += af1.y * bf.x; c5.y += af1.y * bf.y; c5.z += af1.y * bf.z; c5.w += af1.y * bf.w;
            c6.x += af1.z * bf.x; c6.y += af1.z * bf.y; c6.z += af1.z * bf.z; c6.w += af1.z * bf.w;
            c7.x += af1.w * bf.x; c7.y += af1.w * bf.y; c7.z += af1.w * bf.z; c7.w += af1.w * bf.w;
        }
        if (more) {
            int nbuf = buf ^ 1;
            As[nbuf][lk4 + 0][a0row] = na0.x;  As[nbuf][lk4 + 1][a0row] = na0.y;
            As[nbuf][lk4 + 2][a0row] = na0.z;  As[nbuf][lk4 + 3][a0row] = na0.w;
            As[nbuf][lk4 + 0][a1row] = na1.x;  As[nbuf][lk4 + 1][a1row] = na1.y;
            As[nbuf][lk4 + 2][a1row] = na1.z;  As[nbuf][lk4 + 3][a1row] = na1.w;
            Bs[nbuf][lk4 + 0][a0row] = nb.x;   Bs[nbuf][lk4 + 1][a0row] = nb.y;
            Bs[nbuf][lk4 + 2][a0row] = nb.z;   Bs[nbuf][lk4 + 3][a0row] = nb.w;
        }
        __syncthreads();
        buf ^= 1;
    }

    const int orow = brow0 + ty * 8;
    const int ocol = bcol0 + tx * 4;
    if (orow + 0 < Nrows) *(float4*)&Cmat[(long)(orow + 0) * CDIM + ocol] = c0;
    if (orow + 1 < Nrows) *(float4*)&Cmat[(long)(orow + 1) * CDIM + ocol] = c1;
    if (orow + 2 < Nrows) *(float4*)&Cmat[(long)(orow + 2) * CDIM + ocol] = c2;
    if (orow + 3 < Nrows) *(float4*)&Cmat[(long)(orow + 3) * CDIM + ocol] = c3;
    if (orow + 4 < Nrows) *(float4*)&Cmat[(long)(orow + 4) * CDIM + ocol] = c4;
    if (orow + 5 < Nrows) *(float4*)&Cmat[(long)(orow + 5) * CDIM + ocol] = c5;
    if (orow + 6 < Nrows) *(float4*)&Cmat[(long)(orow + 6) * CDIM + ocol] = c6;
    if (orow + 7 < Nrows) *(float4*)&Cmat[(long)(orow + 7) * CDIM + ocol] = c7;
}

// -------- edge -> vertex gather + fused dedupV + degV scale, block per vertex -----------
__global__ __launch_bounds__(CDIM4)
void vertex_gather_kernel(float4* __restrict__ out4, int Me)
{
    __shared__ int s_idx[CAP_V];
    __shared__ int wsum[2];
    __shared__ float s_dv;

    int v = blockIdx.x;
    int tid = threadIdx.x;               // 0..63
    int cnt = d_cur[Me + v];
    int n = min(cnt, CAP_V);
    int base = v * CAP_V;

    // pass 1: cache indices + distinct count (n <= 64, at most one element per thread)
    int mine = 0;
    if (tid < n) {
        int val = d_csrVp[base + tid];
        s_idx[tid] = val;
        bool dup = false;
        for (int j = 0; j < tid; j++)
            if (d_csrVp[base + j] == val) { dup = true; break; }
        if (!dup) mine = 1;
    }
    mine = __reduce_add_sync(0xffffffffu, mine);
    if ((tid & 31) == 0) wsum[tid >> 5] = mine;
    __syncthreads();
    if (tid == 0) {
        int distinct = wsum[0] + wsum[1];
        s_dv = (distinct == 0) ? 1.0f : rsqrtf((float)distinct);
    }
    __syncthreads();

    // pass 2: gather-sum projected edge rows, scale, store
    float dv = s_dv;
    float4 acc = make_float4(0.f, 0.f, 0.f, 0.f);
    int i = 0;
    for (; i + 4 <= n; i += 4) {
        float4 p0 = d_XeP4[(long)s_idx[i + 0] * CDIM4 + tid];
        float4 p1 = d_XeP4[(long)s_idx[i + 1] * CDIM4 + tid];
        float4 p2 = d_XeP4[(long)s_idx[i + 2] * CDIM4 + tid];
        float4 p3 = d_XeP4[(long)s_idx[i + 3] * CDIM4 + tid];
        acc.x += (p0.x + p1.x) + (p2.x + p3.x);
        acc.y += (p0.y + p1.y) + (p2.y + p3.y);
        acc.z += (p0.z + p1.z) + (p2.z + p3.z);
        acc.w += (p0.w + p1.w) + (p2.w + p3.w);
    }
    for (; i < n; i++) {
        float4 p = d_XeP4[(long)s_idx[i] * CDIM4 + tid];
        acc.x += p.x; acc.y += p.y; acc.z += p.z; acc.w += p.w;
    }
    out4[(long)v * CDIM4 + tid] = make_float4(acc.x * dv, acc.y * dv, acc.z * dv, acc.w * dv);
}

// -------------------- launch: 5 nodes, one stream, zero events --------------------
extern "C" void kernel_launch(void* const* d_in, const int* in_sizes, int n_in,
                              void* d_out, int out_size)
{
    const float* X      = (const float*)d_in[0];
    const float* W      = (const float*)d_in[1];
    const int*   vertex = (const int*)d_in[2];
    const int*   edges  = (const int*)d_in[3];
    float* out = (float*)d_out;

    int Nv  = in_sizes[0] / CDIM;             // 20000
    int NNZ = in_sizes[2];                    // 160000
    int Me  = (int)((long)in_sizes[4] / Nv);  // 4000
    int nnz4 = NNZ / 4;
    int wn = (Nv + 31) / 32;

    static float *pY = nullptr, *pXeP = nullptr;
    static int *pCur = nullptr;
    if (pY == nullptr) {
        cudaGetSymbolAddress((void**)&pY,   d_Y4);
        cudaGetSymbolAddress((void**)&pXeP, d_XeP4);
        cudaGetSymbolAddress((void**)&pCur, d_cur);
    }

    cudaMemsetAsync(pCur, 0, (size_t)(Me + Nv) * sizeof(int), 0);
    fill_kernel<<<(nnz4 + 255) / 256, 256>>>((const int4*)vertex, (const int4*)edges, nnz4, Me);
    edge_gather_kernel<<<Me, CDIM4>>>((const float4*)X, wn);
    dim3 ggrid((Me + BM - 1) / BM, CDIM / BN);
    sgemm_kernel<<<ggrid, 256>>>(pY, W, pXeP, Me);
    vertex_gather_kernel<<<Nv, CDIM4>>>((float4*)out, Me);
}